// round 8
// baseline (speedup 1.0000x reference)
#include <cuda_runtime.h>
#include <cuda_bf16.h>
#include <cstdint>

#define BB 8
#define CC 64
#define HWSZ (152 * 272)     // 41344
#define KK 500
#define KPAD 512
#define NSLOTS 32
#define NLBLK (8 * 16 * BB)  // 1024 loss blocks

#define ALPHA 0.25f
#define PROB_MIN 1e-4f

// Scratch (no allocations allowed)
__device__ __align__(16) __nv_bfloat16 g_curb[BB * KPAD * CC];
__device__ __align__(16) __nv_bfloat16 g_preb[BB * KPAD * CC];
__device__ double   g_accs[NSLOTS];   // zero-init; last block resets
__device__ unsigned g_count = 0;

__device__ __forceinline__ uint32_t smem_u32(const void* p) {
    uint32_t a;
    asm("{ .reg .u64 t; cvta.to.shared.u64 t, %1; cvt.u32.u64 %0, t; }"
        : "=r"(a) : "l"(p));
    return a;
}
__device__ __forceinline__ void ldsm_x4(uint32_t& r0, uint32_t& r1,
                                        uint32_t& r2, uint32_t& r3,
                                        uint32_t addr) {
    asm volatile("ldmatrix.sync.aligned.m8n8.x4.shared.b16 {%0,%1,%2,%3}, [%4];"
                 : "=r"(r0), "=r"(r1), "=r"(r2), "=r"(r3) : "r"(addr));
}
__device__ __forceinline__ void ldsm_x2(uint32_t& r0, uint32_t& r1,
                                        uint32_t addr) {
    asm volatile("ldmatrix.sync.aligned.m8n8.x2.shared.b16 {%0,%1}, [%2];"
                 : "=r"(r0), "=r"(r1) : "r"(addr));
}
__device__ __forceinline__ void mma_16816(float* c, const uint32_t* a,
                                          const uint32_t* b) {
    asm volatile(
        "mma.sync.aligned.m16n8k16.row.col.f32.bf16.bf16.f32 "
        "{%0,%1,%2,%3}, {%4,%5,%6,%7}, {%8,%9}, {%0,%1,%2,%3};"
        : "+f"(c[0]), "+f"(c[1]), "+f"(c[2]), "+f"(c[3])
        : "r"(a[0]), "r"(a[1]), "r"(a[2]), "r"(a[3]), "r"(b[0]), "r"(b[1]));
}

__device__ __forceinline__ float loss_fast(float x) {
    float e   = __expf(x);
    float r   = __fdividef(1.0f, 1.0f + e);   // 1 - sigmoid(x)
    float p   = fmaxf(r, PROB_MIN);
    float omp = 1.0f - p;
    return -(1.0f - ALPHA) * omp * omp * __logf(p);
}
__device__ __forceinline__ float loss_gen(float x, bool gt) {
    float e   = __expf(x);
    float r   = __fdividef(1.0f, 1.0f + e);
    float p   = gt ? (1.0f - r) : r;
    p = fmaxf(p, PROB_MIN);
    float a   = gt ? ALPHA : (1.0f - ALPHA);
    float omp = 1.0f - p;
    return -a * omp * omp * __logf(p);
}

// ---------------------------------------------------------------------------
// Gather + bf16 convert. 4 channels/thread; cur/pre split across blockIdx
// (512 blocks -> 2x residency vs round 7). Inline int64/int32 detection.
// ---------------------------------------------------------------------------
__global__ __launch_bounds__(256)
void gather_kernel(const float* __restrict__ cur_reid,
                   const float* __restrict__ pre_reid,
                   const void*  __restrict__ cur_inds,
                   const void*  __restrict__ pre_inds,
                   const void*  __restrict__ cur_cir,
                   const void*  __restrict__ pre_cir,
                   const int*   __restrict__ mask)
{
    __shared__ int s64;
    if (threadIdx.x < 32) {
        long long v = ((const long long*)cur_inds)[threadIdx.x];
        unsigned bad = __ballot_sync(0xffffffffu,
                                     (v < 0) || (v >= (long long)HWSZ));
        if (threadIdx.x == 0) s64 = (bad == 0);
    }
    __syncthreads();

    int tsel = blockIdx.x >> 8;                       // 0 = cur, 1 = pre
    int tid  = (blockIdx.x & 255) * 256 + threadIdx.x;
    if (tid >= BB * KPAD * 16) return;
    int c4  = tid & 15;
    int bk  = tid >> 4;
    int b   = bk >> 9;
    int row = bk & (KPAD - 1);

    const float* src  = tsel ? pre_reid : cur_reid;
    const void*  aidx = tsel ? pre_inds : cur_inds;
    const void*  acir = tsel ? pre_cir  : cur_cir;
    uint2*       dst  = tsel ? (uint2*)g_preb : (uint2*)g_curb;

    if (row >= KK) {
        dst[tid] = make_uint2(0u, 0u);
        return;
    }
    int mk = b * KK + row;
    int m  = mask[mk];
    int ix;
    if (s64) {
        ix = (int)(m ? ((const long long*)aidx)[mk]
                     : ((const long long*)acir)[mk]);
    } else {
        ix = m ? ((const int*)aidx)[mk] : ((const int*)acir)[mk];
    }
    size_t base = ((size_t)b * CC + 4 * c4) * (size_t)HWSZ;
    float v0 = src[base + ix];
    float v1 = src[base + HWSZ + ix];
    float v2 = src[base + 2 * (size_t)HWSZ + ix];
    float v3 = src[base + 3 * (size_t)HWSZ + ix];
    __nv_bfloat162 p0, p1;
    p0.x = __float2bfloat16(v0); p0.y = __float2bfloat16(v1);
    p1.x = __float2bfloat16(v2); p1.y = __float2bfloat16(v3);
    uint2 u;
    u.x = *(uint32_t*)&p0; u.y = *(uint32_t*)&p1;
    dst[tid] = u;
}

// ---------------------------------------------------------------------------
// HMMA loss kernel: 32x64 tile/block, grid (8,16,8)=1024 blocks, 8 warps of
// 16x16 sub-tiles, reg-capped for 6 blocks/SM (~75% occupancy).
// Last block finalizes (spread slots + cheap count atomic).
// ---------------------------------------------------------------------------
__global__ __launch_bounds__(256, 6)
void loss_kernel(const int* __restrict__ mask, float* __restrict__ out)
{
    __shared__ __align__(128) uint8_t smA[32 * 128];  // 32 rows x 64 bf16
    __shared__ __align__(128) uint8_t smB[64 * 128];  // 64 rows x 64 bf16
    __shared__ float wsum[8];

    int t   = threadIdx.x;
    int w   = t >> 5;
    int lid = t & 31;
    int b   = blockIdx.z;
    int it  = blockIdx.y;                 // 16 row-tiles of 32
    int jt  = blockIdx.x;                 // 8 col-tiles of 64
    int i0  = it * 32;
    int j0  = jt * 64;

    // Stage tiles: A 256 x 16B, B 512 x 16B; swizzle chunk ^= (row & 7).
    const uint4* srcA = (const uint4*)(g_curb + ((size_t)b * KPAD + i0) * CC);
    const uint4* srcB = (const uint4*)(g_preb + ((size_t)b * KPAD + j0) * CC);
    {
        int u  = t;                       // 0..255 -> A
        int r  = u >> 3;
        int c  = u & 7;
        int sw = (r << 7) + ((c ^ (r & 7)) << 4);
        *(uint4*)(smA + sw) = srcA[u];
        #pragma unroll
        for (int k = 0; k < 2; k++) {
            int v  = t + 256 * k;         // 0..511 -> B
            int rb = v >> 3;
            int cb = v & 7;
            int sb = (rb << 7) + ((cb ^ (rb & 7)) << 4);
            *(uint4*)(smB + sb) = srcB[v];
        }
    }
    __syncthreads();

    uint32_t baseA = smem_u32(smA);
    uint32_t baseB = smem_u32(smB);

    int wm = w & 1;        // 2 x 16 rows
    int wn = w >> 1;       // 4 x 16 cols

    float acc[2][4] = {};  // [fn][reg]
    #pragma unroll
    for (int ks = 0; ks < 4; ks++) {
        int kc = ks * 2;
        uint32_t a[4];
        {
            int row = wm * 16 + (lid & 15);
            int ch  = kc + (lid >> 4);
            uint32_t addr = baseA + (row << 7) + ((ch ^ (row & 7)) << 4);
            ldsm_x4(a[0], a[1], a[2], a[3], addr);
        }
        uint32_t bf[2][2];
        #pragma unroll
        for (int fn = 0; fn < 2; fn++) {
            int l8  = lid & 15;
            int row = wn * 16 + fn * 8 + (l8 & 7);
            int ch  = kc + (l8 >> 3);
            uint32_t addr = baseB + (row << 7) + ((ch ^ (row & 7)) << 4);
            ldsm_x2(bf[fn][0], bf[fn][1], addr);
        }
        #pragma unroll
        for (int fn = 0; fn < 2; fn++)
            mma_16816(acc[fn], a, bf[fn]);
    }

    // Epilogue: c0:(i,j) c1:(i,j+1) c2:(i+8,j) c3:(i+8,j+1);
    // i = i0+wm*16+gid(+8), j = j0+wn*16+fn*8+2*tig(+1)
    int gid = lid >> 2;
    int tig = lid & 3;
    float lsum = 0.0f;

    bool interior = (it < 15) && (jt < 7);
    bool diag     = (jt == (it >> 1));    // tile contains diagonal elements

    if (interior && !diag) {
        #pragma unroll
        for (int fn = 0; fn < 2; fn++)
            #pragma unroll
            for (int rg = 0; rg < 4; rg++)
                lsum += loss_fast(acc[fn][rg]);
    } else {
        int ib = i0 + wm * 16 + gid;
        int m0 = (diag && ib     < KK) ? mask[b * KK + ib]     : 0;
        int m8 = (diag && ib + 8 < KK) ? mask[b * KK + ib + 8] : 0;
        #pragma unroll
        for (int fn = 0; fn < 2; fn++) {
            int jb = j0 + wn * 16 + fn * 8 + 2 * tig;
            #pragma unroll
            for (int rg = 0; rg < 4; rg++) {
                int i = ib + (rg >> 1) * 8;
                int j = jb + (rg & 1);
                if (i < KK && j < KK) {
                    bool gt = diag && (i == j) &&
                              (((rg >> 1) ? m8 : m0) != 0);
                    lsum += loss_gen(acc[fn][rg], gt);
                }
            }
        }
    }

    #pragma unroll
    for (int o = 16; o > 0; o >>= 1)
        lsum += __shfl_xor_sync(0xffffffffu, lsum, o);
    if (lid == 0) wsum[w] = lsum;
    __syncthreads();

    if (t == 0) {
        float v = 0.f;
        #pragma unroll
        for (int k = 0; k < 8; k++) v += wsum[k];
        int bid = blockIdx.x + 8 * (blockIdx.y + 16 * blockIdx.z);
        atomicAdd(&g_accs[bid & (NSLOTS - 1)], (double)v);
        __threadfence();
        unsigned old = atomicAdd(&g_count, 1u);
        if (old == NLBLK - 1) {           // last block: finalize + reset
            double tot = 0.0;
            #pragma unroll
            for (int s = 0; s < NSLOTS; s++) {
                tot += g_accs[s];
                g_accs[s] = 0.0;
            }
            out[0] = (float)(tot / ((double)BB * KK * KK));
            __threadfence();
            g_count = 0u;
        }
    }
}

extern "C" void kernel_launch(void* const* d_in, const int* in_sizes, int n_in,
                              void* d_out, int out_size)
{
    const float* cur_reid = (const float*)d_in[0];
    const float* pre_reid = (const float*)d_in[1];
    const int*   mask     = (const int*)d_in[6];
    float* out = (float*)d_out;

    gather_kernel<<<512, 256>>>(cur_reid, pre_reid,
                                d_in[2], d_in[3], d_in[4], d_in[5], mask);

    dim3 grid(8, 16, BB);
    loss_kernel<<<grid, 256>>>(mask, out);
}